// round 1
// baseline (speedup 1.0000x reference)
#include <cuda_runtime.h>
#include <cuda_bf16.h>
#include <cstdint>
#include <math.h>

#define B_SZ 8192
#define D_SZ 256
#define INV_T (1.0f / 0.07f)

// ---------------- scratch (no allocations allowed) ----------------
__device__ __align__(16) __nv_bfloat16 g_q[B_SZ * D_SZ];   // 4 MB
__device__ __align__(16) __nv_bfloat16 g_t[B_SZ * D_SZ];   // 4 MB
__device__ float g_pos[B_SZ];
__device__ float g_pm[4 * B_SZ];   // per-colsplit row max
__device__ float g_ps[4 * B_SZ];   // per-colsplit row sumexp

// ---------------- kernel 1: normalize ----------------
// 1 warp per row. lane handles cols [lane*4, lane*4+4) and [128+lane*4, ...)
__global__ __launch_bounds__(256) void norm_kernel(const float* __restrict__ h,
                                                   const float* __restrict__ r,
                                                   const float* __restrict__ t) {
    int wid = threadIdx.x >> 5;
    int lane = threadIdx.x & 31;
    int row = blockIdx.x * 8 + wid;

    const float4* h4 = (const float4*)h;
    const float4* r4 = (const float4*)r;
    const float4* t4 = (const float4*)t;
    int base = row * 64;  // float4 units per row = 256/4

    float4 ha = h4[base + lane];
    float4 hb = h4[base + 32 + lane];
    float4 ra = r4[base + lane];
    float4 rb = r4[base + 32 + lane];
    float4 va = make_float4(ha.x + ra.x, ha.y + ra.y, ha.z + ra.z, ha.w + ra.w);
    float4 vb = make_float4(hb.x + rb.x, hb.y + rb.y, hb.z + rb.z, hb.w + rb.w);

    float ss = va.x * va.x + va.y * va.y + va.z * va.z + va.w * va.w +
               vb.x * vb.x + vb.y * vb.y + vb.z * vb.z + vb.w * vb.w;
#pragma unroll
    for (int o = 16; o > 0; o >>= 1) ss += __shfl_xor_sync(0xffffffffu, ss, o);
    float qinv = rsqrtf(fmaxf(ss, 1e-24f));

    float4 ta = t4[base + lane];
    float4 tb = t4[base + 32 + lane];
    float ts = ta.x * ta.x + ta.y * ta.y + ta.z * ta.z + ta.w * ta.w +
               tb.x * tb.x + tb.y * tb.y + tb.z * tb.z + tb.w * tb.w;
#pragma unroll
    for (int o = 16; o > 0; o >>= 1) ts += __shfl_xor_sync(0xffffffffu, ts, o);
    float tinv = rsqrtf(fmaxf(ts, 1e-24f));

    float qa0 = va.x * qinv, qa1 = va.y * qinv, qa2 = va.z * qinv, qa3 = va.w * qinv;
    float qb0 = vb.x * qinv, qb1 = vb.y * qinv, qb2 = vb.z * qinv, qb3 = vb.w * qinv;
    float ta0 = ta.x * tinv, ta1 = ta.y * tinv, ta2 = ta.z * tinv, ta3 = ta.w * tinv;
    float tb0 = tb.x * tinv, tb1 = tb.y * tinv, tb2 = tb.z * tinv, tb3 = tb.w * tinv;

    // write bf16 q, t  (pairs)
    __nv_bfloat162* q2 = (__nv_bfloat162*)(g_q + row * D_SZ);
    __nv_bfloat162* t2 = (__nv_bfloat162*)(g_t + row * D_SZ);
    int c2 = lane * 2;  // bf162 index for cols lane*4..
    q2[c2]      = __floats2bfloat162_rn(qa0, qa1);
    q2[c2 + 1]  = __floats2bfloat162_rn(qa2, qa3);
    q2[c2 + 64] = __floats2bfloat162_rn(qb0, qb1);
    q2[c2 + 65] = __floats2bfloat162_rn(qb2, qb3);
    t2[c2]      = __floats2bfloat162_rn(ta0, ta1);
    t2[c2 + 1]  = __floats2bfloat162_rn(ta2, ta3);
    t2[c2 + 64] = __floats2bfloat162_rn(tb0, tb1);
    t2[c2 + 65] = __floats2bfloat162_rn(tb2, tb3);

    // exact fp32 diagonal (positive) similarity
    float p = qa0 * ta0 + qa1 * ta1 + qa2 * ta2 + qa3 * ta3 +
              qb0 * tb0 + qb1 * tb1 + qb2 * tb2 + qb3 * tb3;
#pragma unroll
    for (int o = 16; o > 0; o >>= 1) p += __shfl_xor_sync(0xffffffffu, p, o);
    if (lane == 0) g_pos[row] = p * INV_T;
}

// ---------------- kernel 2: fused GEMM + online LSE ----------------
// grid (64 row tiles, 4 col splits), 256 threads.
// CTA tile: 128 rows x 64 cols per chunk, 32 chunks per colsplit (2048 cols).
#define SQ 264   // smem row stride in bf16 elements (256 + 8 pad)
#define SS 66    // S tile row stride in floats

__device__ __forceinline__ void mma_bf16(float c[4], const uint32_t a[4], const uint32_t b[2]) {
    asm volatile(
        "mma.sync.aligned.m16n8k16.row.col.f32.bf16.bf16.f32 "
        "{%0,%1,%2,%3}, {%4,%5,%6,%7}, {%8,%9}, {%0,%1,%2,%3};\n"
        : "+f"(c[0]), "+f"(c[1]), "+f"(c[2]), "+f"(c[3])
        : "r"(a[0]), "r"(a[1]), "r"(a[2]), "r"(a[3]), "r"(b[0]), "r"(b[1]));
}

__global__ __launch_bounds__(256, 1) void gemm_lse_kernel() {
    extern __shared__ char smem[];
    __nv_bfloat16* qs = (__nv_bfloat16*)smem;               // [128][SQ]
    __nv_bfloat16* tss = qs + 128 * SQ;                      // [64][SQ]
    float* S = (float*)(tss + 64 * SQ);                      // [128][SS]

    const int tid = threadIdx.x;
    const int wid = tid >> 5;
    const int lane = tid & 31;
    const int row0 = blockIdx.x * 128;
    const int csplit = blockIdx.y;

    // load q tile (128x256 bf16) once
    for (int i = tid; i < 128 * 32; i += 256) {
        int rr = i >> 5;
        int c8 = (i & 31) * 8;
        *(uint4*)(qs + rr * SQ + c8) = *(const uint4*)(g_q + (row0 + rr) * D_SZ + c8);
    }

    // warp tile: 32x32; warps as 4 (rows) x 2 (cols)
    const int wr = (wid >> 1) * 32;
    const int wc = (wid & 1) * 32;

    // ldmatrix lane base addresses
    uint32_t aAddr[2], bAddr[4];
#pragma unroll
    for (int mt = 0; mt < 2; mt++) {
        int rrow = wr + mt * 16 + (lane & 15);
        int coff = (lane >> 4) * 8;
        aAddr[mt] = (uint32_t)__cvta_generic_to_shared(qs + rrow * SQ + coff);
    }
#pragma unroll
    for (int nt = 0; nt < 4; nt++) {
        int rrow = wc + nt * 8 + (lane & 7);
        int coff = ((lane >> 3) & 1) * 8;
        bAddr[nt] = (uint32_t)__cvta_generic_to_shared(tss + rrow * SQ + coff);
    }

    float rm = -INFINITY, rs = 0.0f;

    for (int ci = 0; ci < 32; ci++) {
        int col0 = csplit * 2048 + ci * 64;
        // load t chunk (64 x 256 bf16)
        for (int i = tid; i < 64 * 32; i += 256) {
            int rr = i >> 5;
            int c8 = (i & 31) * 8;
            *(uint4*)(tss + rr * SQ + c8) = *(const uint4*)(g_t + (col0 + rr) * D_SZ + c8);
        }
        __syncthreads();

        float acc[2][4][4];
#pragma unroll
        for (int mt = 0; mt < 2; mt++)
#pragma unroll
            for (int nt = 0; nt < 4; nt++)
#pragma unroll
                for (int k = 0; k < 4; k++) acc[mt][nt][k] = 0.0f;

#pragma unroll
        for (int ks = 0; ks < 16; ks++) {
            uint32_t a[2][4];
            uint32_t b[4][2];
#pragma unroll
            for (int mt = 0; mt < 2; mt++) {
                asm volatile(
                    "ldmatrix.sync.aligned.m8n8.x4.shared.b16 {%0,%1,%2,%3}, [%4];\n"
                    : "=r"(a[mt][0]), "=r"(a[mt][1]), "=r"(a[mt][2]), "=r"(a[mt][3])
                    : "r"(aAddr[mt] + ks * 32));
            }
#pragma unroll
            for (int nt = 0; nt < 4; nt++) {
                asm volatile(
                    "ldmatrix.sync.aligned.m8n8.x2.shared.b16 {%0,%1}, [%2];\n"
                    : "=r"(b[nt][0]), "=r"(b[nt][1])
                    : "r"(bAddr[nt] + ks * 32));
            }
#pragma unroll
            for (int mt = 0; mt < 2; mt++)
#pragma unroll
                for (int nt = 0; nt < 4; nt++) mma_bf16(acc[mt][nt], a[mt], b[nt]);
        }
        __syncthreads();  // prev LSE done reading S; all warps done reading tss

        // store scaled S tile
#pragma unroll
        for (int mt = 0; mt < 2; mt++) {
#pragma unroll
            for (int nt = 0; nt < 4; nt++) {
                int r0 = wr + mt * 16 + (lane >> 2);
                int c0 = wc + nt * 8 + (lane & 3) * 2;
                S[r0 * SS + c0]       = acc[mt][nt][0] * INV_T;
                S[r0 * SS + c0 + 1]   = acc[mt][nt][1] * INV_T;
                S[(r0 + 8) * SS + c0]     = acc[mt][nt][2] * INV_T;
                S[(r0 + 8) * SS + c0 + 1] = acc[mt][nt][3] * INV_T;
            }
        }
        __syncthreads();

        // online LSE update: 128 threads, one per row
        if (tid < 128) {
            const float* Sr = S + tid * SS;
            float cmax = Sr[0];
#pragma unroll 8
            for (int j = 1; j < 64; j++) cmax = fmaxf(cmax, Sr[j]);
            float nm = fmaxf(rm, cmax);
            float a2 = rs * __expf(rm - nm);
#pragma unroll 8
            for (int j = 0; j < 64; j++) a2 += __expf(Sr[j] - nm);
            rs = a2;
            rm = nm;
        }
        __syncthreads();
    }

    if (tid < 128) {
        g_pm[csplit * B_SZ + row0 + tid] = rm;
        g_ps[csplit * B_SZ + row0 + tid] = rs;
    }
}

// ---------------- kernel 3: combine + mean ----------------
__global__ __launch_bounds__(256) void reduce_kernel(float* __restrict__ out) {
    __shared__ double red[256];
    int tid = threadIdx.x;
    double acc = 0.0;
    for (int rI = tid; rI < B_SZ; rI += 256) {
        float m0 = g_pm[rI], m1 = g_pm[B_SZ + rI], m2 = g_pm[2 * B_SZ + rI], m3 = g_pm[3 * B_SZ + rI];
        float M = fmaxf(fmaxf(m0, m1), fmaxf(m2, m3));
        float Ssum = g_ps[rI] * __expf(m0 - M) + g_ps[B_SZ + rI] * __expf(m1 - M) +
                     g_ps[2 * B_SZ + rI] * __expf(m2 - M) + g_ps[3 * B_SZ + rI] * __expf(m3 - M);
        float lse = M + logf(Ssum);
        acc += (double)(lse - g_pos[rI]);
    }
    red[tid] = acc;
    __syncthreads();
    for (int o = 128; o > 0; o >>= 1) {
        if (tid < o) red[tid] += red[tid + o];
        __syncthreads();
    }
    if (tid == 0) out[0] = (float)(red[0] / (double)B_SZ);
}

// ---------------- launch ----------------
extern "C" void kernel_launch(void* const* d_in, const int* in_sizes, int n_in,
                              void* d_out, int out_size) {
    const float* h = (const float*)d_in[0];
    const float* r = (const float*)d_in[1];
    const float* t = (const float*)d_in[2];
    float* out = (float*)d_out;

    static bool attr_set = false;
    if (!attr_set) {
        cudaFuncSetAttribute(gemm_lse_kernel, cudaFuncAttributeMaxDynamicSharedMemorySize,
                             (128 * SQ + 64 * SQ) * 2 + 128 * SS * 4);
        attr_set = true;
    }

    norm_kernel<<<B_SZ / 8, 256>>>(h, r, t);
    gemm_lse_kernel<<<dim3(64, 4), 256, (128 * SQ + 64 * SQ) * 2 + 128 * SS * 4>>>();
    reduce_kernel<<<1, 256>>>(out);
}

// round 3
// speedup vs baseline: 1.9108x; 1.9108x over previous
#include <cuda_runtime.h>
#include <cuda_bf16.h>
#include <cstdint>
#include <math.h>

#define B_SZ 8192
#define D_SZ 256
#define INV_T (1.0f / 0.07f)

// ---------------- scratch (no allocations allowed) ----------------
__device__ __align__(16) __nv_bfloat16 g_q[B_SZ * D_SZ];   // 4 MB
__device__ __align__(16) __nv_bfloat16 g_t[B_SZ * D_SZ];   // 4 MB
__device__ float g_pos[B_SZ];
__device__ float g_ps[2 * B_SZ];   // per-colsplit row sum of exp

// ---------------- kernel 1: normalize ----------------
__global__ __launch_bounds__(256) void norm_kernel(const float* __restrict__ h,
                                                   const float* __restrict__ r,
                                                   const float* __restrict__ t) {
    int wid = threadIdx.x >> 5;
    int lane = threadIdx.x & 31;
    int row = blockIdx.x * 8 + wid;

    const float4* h4 = (const float4*)h;
    const float4* r4 = (const float4*)r;
    const float4* t4 = (const float4*)t;
    int base = row * 64;

    float4 ha = h4[base + lane];
    float4 hb = h4[base + 32 + lane];
    float4 ra = r4[base + lane];
    float4 rb = r4[base + 32 + lane];
    float4 va = make_float4(ha.x + ra.x, ha.y + ra.y, ha.z + ra.z, ha.w + ra.w);
    float4 vb = make_float4(hb.x + rb.x, hb.y + rb.y, hb.z + rb.z, hb.w + rb.w);

    float ss = va.x * va.x + va.y * va.y + va.z * va.z + va.w * va.w +
               vb.x * vb.x + vb.y * vb.y + vb.z * vb.z + vb.w * vb.w;
#pragma unroll
    for (int o = 16; o > 0; o >>= 1) ss += __shfl_xor_sync(0xffffffffu, ss, o);
    float qinv = rsqrtf(fmaxf(ss, 1e-24f));

    float4 ta = t4[base + lane];
    float4 tb = t4[base + 32 + lane];
    float ts = ta.x * ta.x + ta.y * ta.y + ta.z * ta.z + ta.w * ta.w +
               tb.x * tb.x + tb.y * tb.y + tb.z * tb.z + tb.w * tb.w;
#pragma unroll
    for (int o = 16; o > 0; o >>= 1) ts += __shfl_xor_sync(0xffffffffu, ts, o);
    float tinv = rsqrtf(fmaxf(ts, 1e-24f));

    float qa0 = va.x * qinv, qa1 = va.y * qinv, qa2 = va.z * qinv, qa3 = va.w * qinv;
    float qb0 = vb.x * qinv, qb1 = vb.y * qinv, qb2 = vb.z * qinv, qb3 = vb.w * qinv;
    float ta0 = ta.x * tinv, ta1 = ta.y * tinv, ta2 = ta.z * tinv, ta3 = ta.w * tinv;
    float tb0 = tb.x * tinv, tb1 = tb.y * tinv, tb2 = tb.z * tinv, tb3 = tb.w * tinv;

    __nv_bfloat162* q2 = (__nv_bfloat162*)(g_q + row * D_SZ);
    __nv_bfloat162* t2 = (__nv_bfloat162*)(g_t + row * D_SZ);
    int c2 = lane * 2;
    q2[c2]      = __floats2bfloat162_rn(qa0, qa1);
    q2[c2 + 1]  = __floats2bfloat162_rn(qa2, qa3);
    q2[c2 + 64] = __floats2bfloat162_rn(qb0, qb1);
    q2[c2 + 65] = __floats2bfloat162_rn(qb2, qb3);
    t2[c2]      = __floats2bfloat162_rn(ta0, ta1);
    t2[c2 + 1]  = __floats2bfloat162_rn(ta2, ta3);
    t2[c2 + 64] = __floats2bfloat162_rn(tb0, tb1);
    t2[c2 + 65] = __floats2bfloat162_rn(tb2, tb3);

    float p = qa0 * ta0 + qa1 * ta1 + qa2 * ta2 + qa3 * ta3 +
              qb0 * tb0 + qb1 * tb1 + qb2 * tb2 + qb3 * tb3;
#pragma unroll
    for (int o = 16; o > 0; o >>= 1) p += __shfl_xor_sync(0xffffffffu, p, o);
    if (lane == 0) g_pos[row] = p * INV_T;
}

// ---------------- kernel 2: HMMA GEMM + fused exp-sum ----------------
// grid (64 row-tiles, 2 col-splits), 256 threads (8 warps, 4x2).
// CTA: q tile 128x256 resident; 32 chunks of t (128 rows x 256), cp.async
// double buffered. Chunk compute: 128x128 S in registers, exp applied in-place.
#define NCH 32
#define SQ 264                               // bf16 elems per smem row (+pad)
#define TBYTES (128 * SQ * 2)                // 67584 B per tile
#define QOFF 0
#define T0OFF TBYTES
#define T1OFF (2 * TBYTES)
#define SMEM_TOTAL (3 * TBYTES)

__device__ __forceinline__ void cp16(uint32_t dst, const void* src) {
    asm volatile("cp.async.cg.shared.global [%0], [%1], 16;\n" :: "r"(dst), "l"(src));
}
__device__ __forceinline__ void cp_commit() {
    asm volatile("cp.async.commit_group;\n" ::: "memory");
}
template <int N>
__device__ __forceinline__ void cp_wait() {
    asm volatile("cp.async.wait_group %0;\n" :: "n"(N) : "memory");
}

__device__ __forceinline__ void mma_bf16(float c[4], const uint32_t a[4], const uint32_t* b) {
    asm volatile(
        "mma.sync.aligned.m16n8k16.row.col.f32.bf16.bf16.f32 "
        "{%0,%1,%2,%3}, {%4,%5,%6,%7}, {%8,%9}, {%0,%1,%2,%3};\n"
        : "+f"(c[0]), "+f"(c[1]), "+f"(c[2]), "+f"(c[3])
        : "r"(a[0]), "r"(a[1]), "r"(a[2]), "r"(a[3]), "r"(b[0]), "r"(b[1]));
}

__global__ __launch_bounds__(256, 1) void gemm_lse_kernel() {
    extern __shared__ char smem[];
    __nv_bfloat16* qs = (__nv_bfloat16*)(smem + QOFF);

    const int tid = threadIdx.x;
    const int wid = tid >> 5;
    const int lane = tid & 31;
    const int row0 = blockIdx.x * 128;
    const int csplit = blockIdx.y;
    const int col_base = csplit * 4096;

    // ---- load q tile (resident) + t0 (group 0), t1 (group 1) via cp.async ----
    {
        const __nv_bfloat16* qsrc = g_q + (size_t)row0 * D_SZ;
        const __nv_bfloat16* tsrc = g_t + (size_t)col_base * D_SZ;
        for (int i = tid; i < 128 * 32; i += 256) {
            int rr = i >> 5;
            int c8 = (i & 31) * 8;
            uint32_t so = (uint32_t)__cvta_generic_to_shared(smem) + (rr * SQ + c8) * 2;
            cp16(so + QOFF, qsrc + rr * D_SZ + c8);
            cp16(so + T0OFF, tsrc + rr * D_SZ + c8);
        }
        cp_commit();
        const __nv_bfloat16* tsrc1 = g_t + (size_t)(col_base + 128) * D_SZ;
        for (int i = tid; i < 128 * 32; i += 256) {
            int rr = i >> 5;
            int c8 = (i & 31) * 8;
            uint32_t so = (uint32_t)__cvta_generic_to_shared(smem) + T1OFF + (rr * SQ + c8) * 2;
            cp16(so, tsrc1 + rr * D_SZ + c8);
        }
        cp_commit();
    }

    // warp tile: 32 rows x 64 cols; warps 4 (rows) x 2 (cols)
    const int wr = (wid >> 1) * 32;
    const int wc = (wid & 1) * 64;

    // A ldmatrix addresses (x4: 16 rows, 2 k-halves)
    uint32_t aAddr[2];
#pragma unroll
    for (int mt = 0; mt < 2; mt++) {
        int rrow = wr + mt * 16 + (lane & 15);
        int coff = (lane >> 4) * 8;
        aAddr[mt] = (uint32_t)__cvta_generic_to_shared(qs + rrow * SQ + coff);
    }
    // B ldmatrix addresses (x4 covers 2 n8 frags x 2 k-halves) — per t buffer
    uint32_t bAddr[2][4];
#pragma unroll
    for (int p = 0; p < 4; p++) {
        int nt = 2 * p + (lane >> 4);
        int khalf = (lane >> 3) & 1;
        int rrow = wc + nt * 8 + (lane & 7);
        uint32_t off = (uint32_t)(rrow * SQ + khalf * 8) * 2;
        bAddr[0][p] = (uint32_t)__cvta_generic_to_shared(smem) + T0OFF + off;
        bAddr[1][p] = (uint32_t)__cvta_generic_to_shared(smem) + T1OFF + off;
    }

    float rsum[4] = {0.f, 0.f, 0.f, 0.f};

    for (int ci = 0; ci < NCH; ci++) {
        if (ci == NCH - 1) cp_wait<0>(); else cp_wait<1>();
        __syncthreads();

        const int cb = ci & 1;
        float acc[2][8][4];
#pragma unroll
        for (int mt = 0; mt < 2; mt++)
#pragma unroll
            for (int nt = 0; nt < 8; nt++)
#pragma unroll
                for (int k = 0; k < 4; k++) acc[mt][nt][k] = 0.0f;

#pragma unroll
        for (int ks = 0; ks < 16; ks++) {
            uint32_t a[2][4];
            uint32_t b[8][2];
#pragma unroll
            for (int mt = 0; mt < 2; mt++) {
                asm volatile(
                    "ldmatrix.sync.aligned.m8n8.x4.shared.b16 {%0,%1,%2,%3}, [%4];\n"
                    : "=r"(a[mt][0]), "=r"(a[mt][1]), "=r"(a[mt][2]), "=r"(a[mt][3])
                    : "r"(aAddr[mt] + ks * 32));
            }
#pragma unroll
            for (int p = 0; p < 4; p++) {
                asm volatile(
                    "ldmatrix.sync.aligned.m8n8.x4.shared.b16 {%0,%1,%2,%3}, [%4];\n"
                    : "=r"(b[2 * p][0]), "=r"(b[2 * p][1]),
                      "=r"(b[2 * p + 1][0]), "=r"(b[2 * p + 1][1])
                    : "r"(bAddr[cb][p] + ks * 32));
            }
#pragma unroll
            for (int mt = 0; mt < 2; mt++)
#pragma unroll
                for (int nt = 0; nt < 8; nt++) mma_bf16(acc[mt][nt], a[mt], b[nt]);
        }

        // fused epilogue: exp on accumulators, accumulate per-thread row sums
#pragma unroll
        for (int mt = 0; mt < 2; mt++) {
            float s0 = 0.f, s1 = 0.f;
#pragma unroll
            for (int nt = 0; nt < 8; nt++) {
                s0 += __expf(acc[mt][nt][0] * INV_T) + __expf(acc[mt][nt][1] * INV_T);
                s1 += __expf(acc[mt][nt][2] * INV_T) + __expf(acc[mt][nt][3] * INV_T);
            }
            rsum[mt * 2]     += s0;
            rsum[mt * 2 + 1] += s1;
        }

        __syncthreads();
        // refill this buffer with chunk ci+2
        if (ci + 2 < NCH) {
            const __nv_bfloat16* tsrc = g_t + (size_t)(col_base + (ci + 2) * 128) * D_SZ;
            uint32_t base = (uint32_t)__cvta_generic_to_shared(smem) + (cb ? T1OFF : T0OFF);
            for (int i = tid; i < 128 * 32; i += 256) {
                int rr = i >> 5;
                int c8 = (i & 31) * 8;
                cp16(base + (rr * SQ + c8) * 2, tsrc + rr * D_SZ + c8);
            }
            cp_commit();
        }
    }

    // ---- cross-lane (same row) then cross-warp (col halves) reduction ----
#pragma unroll
    for (int i = 0; i < 4; i++) {
        float v = rsum[i];
        v += __shfl_xor_sync(0xffffffffu, v, 1);
        v += __shfl_xor_sync(0xffffffffu, v, 2);
        rsum[i] = v;
    }
    __syncthreads();
    float* red = (float*)smem;   // 128 rows x 2 col-halves
    if ((lane & 3) == 0) {
        int g = lane >> 2;
#pragma unroll
        for (int i = 0; i < 4; i++) {
            int rrow = wr + (i >> 1) * 16 + (i & 1) * 8 + g;
            red[rrow * 2 + (wid & 1)] = rsum[i];
        }
    }
    __syncthreads();
    if (tid < 128)
        g_ps[csplit * B_SZ + row0 + tid] = red[tid * 2] + red[tid * 2 + 1];
}

// ---------------- kernel 3: combine + mean ----------------
__global__ __launch_bounds__(256) void reduce_kernel(float* __restrict__ out) {
    __shared__ double red[256];
    int tid = threadIdx.x;
    double acc = 0.0;
    for (int rI = tid; rI < B_SZ; rI += 256) {
        float s = g_ps[rI] + g_ps[B_SZ + rI];
        acc += (double)(logf(s) - g_pos[rI]);
    }
    red[tid] = acc;
    __syncthreads();
    for (int o = 128; o > 0; o >>= 1) {
        if (tid < o) red[tid] += red[tid + o];
        __syncthreads();
    }
    if (tid == 0) out[0] = (float)(red[0] / (double)B_SZ);
}

// ---------------- launch ----------------
extern "C" void kernel_launch(void* const* d_in, const int* in_sizes, int n_in,
                              void* d_out, int out_size) {
    const float* h = (const float*)d_in[0];
    const float* r = (const float*)d_in[1];
    const float* t = (const float*)d_in[2];
    float* out = (float*)d_out;

    static bool attr_set = false;
    if (!attr_set) {
        cudaFuncSetAttribute(gemm_lse_kernel, cudaFuncAttributeMaxDynamicSharedMemorySize,
                             SMEM_TOTAL);
        attr_set = true;
    }

    norm_kernel<<<B_SZ / 8, 256>>>(h, r, t);
    gemm_lse_kernel<<<dim3(64, 2), 256, SMEM_TOTAL>>>();
    reduce_kernel<<<1, 256>>>(out);
}